// round 1
// baseline (speedup 1.0000x reference)
#include <cuda_runtime.h>
#include <cuda_bf16.h>

#define HID 1024
#define BB  4
#define SS  2048
#define HH  16
#define DD  64
#define MTOT (BB*SS)   // 8192

// Scratch (allocation-free rule: __device__ globals)
__device__ float g_Q[(size_t)BB*HH*SS*DD];     // [B*H, S, D]
__device__ float g_K[(size_t)BB*HH*SS*DD];
__device__ float g_V[(size_t)BB*HH*SS*DD];
__device__ float g_attn[(size_t)MTOT*HID];     // [B*S, HID]

// ---------------------------------------------------------------------------
// Fused QKV projection:  out = x @ W.T + b, written as [B,H,S,D]
// C[m,n] = sum_k X[m,k]*W[n,k] + b[n]   (both operands K-contiguous)
// Tiles: 128x128x16, 256 threads, 8x8 per-thread register tile.
// ---------------------------------------------------------------------------
__global__ __launch_bounds__(256) void qkv_kernel(
    const float* __restrict__ X,
    const float* __restrict__ Wq, const float* __restrict__ bq,
    const float* __restrict__ Wk, const float* __restrict__ bk,
    const float* __restrict__ Wv, const float* __restrict__ bv)
{
    const float* W; const float* bias; float* out;
    if (blockIdx.z == 0)      { W = Wq; bias = bq; out = g_Q; }
    else if (blockIdx.z == 1) { W = Wk; bias = bk; out = g_K; }
    else                      { W = Wv; bias = bv; out = g_V; }

    __shared__ float Xs[16][128];   // [k][m]
    __shared__ float Ws[16][128];   // [k][n]

    const int m0 = blockIdx.x * 128;
    const int n0 = blockIdx.y * 128;
    const int tid = threadIdx.x;
    const int tm = tid >> 4;        // 0..15
    const int tn = tid & 15;        // 0..15

    float acc[8][8];
    #pragma unroll
    for (int i = 0; i < 8; i++)
        #pragma unroll
        for (int j = 0; j < 8; j++) acc[i][j] = 0.f;

    for (int k0 = 0; k0 < HID; k0 += 16) {
        #pragma unroll
        for (int it = 0; it < 2; it++) {
            int f   = tid + it * 256;      // 0..511 float4 slots
            int row = f >> 2;              // 0..127
            int c4  = f & 3;               // 0..3
            float4 xv = *(const float4*)&X[(size_t)(m0 + row) * HID + k0 + c4 * 4];
            Xs[c4*4+0][row] = xv.x; Xs[c4*4+1][row] = xv.y;
            Xs[c4*4+2][row] = xv.z; Xs[c4*4+3][row] = xv.w;
            float4 wv = *(const float4*)&W[(size_t)(n0 + row) * HID + k0 + c4 * 4];
            Ws[c4*4+0][row] = wv.x; Ws[c4*4+1][row] = wv.y;
            Ws[c4*4+2][row] = wv.z; Ws[c4*4+3][row] = wv.w;
        }
        __syncthreads();

        #pragma unroll
        for (int kk = 0; kk < 16; kk++) {
            float a[8], w[8];
            *(float4*)&a[0] = *(float4*)&Xs[kk][tm*8];
            *(float4*)&a[4] = *(float4*)&Xs[kk][tm*8+4];
            *(float4*)&w[0] = *(float4*)&Ws[kk][tn*8];
            *(float4*)&w[4] = *(float4*)&Ws[kk][tn*8+4];
            #pragma unroll
            for (int i = 0; i < 8; i++)
                #pragma unroll
                for (int j = 0; j < 8; j++)
                    acc[i][j] = fmaf(a[i], w[j], acc[i][j]);
        }
        __syncthreads();
    }

    // epilogue: add bias, scatter to [B,H,S,D]
    #pragma unroll
    for (int i = 0; i < 8; i++) {
        int m = m0 + tm*8 + i;
        int b = m / SS, s = m % SS;
        #pragma unroll
        for (int j = 0; j < 8; j++) {
            int n = n0 + tn*8 + j;
            int h = n >> 6, d = n & 63;
            out[(((size_t)(b*HH) + h) * SS + s) * DD + d] = acc[i][j] + bias[n];
        }
    }
}

// ---------------------------------------------------------------------------
// Flash attention, fp32. Per block: 64 queries of one (b,h); loop 64-key chunks.
// Masked-key logit = -50 (masked_fill(-inf) then clamp(-50,50)); unmasked
// logits clamped to [-50,50]. Online softmax.
// Thread map: 16x16 grid; thread (ty,tx) owns scores[4q x 4k] and O[4q x 4d].
// ---------------------------------------------------------------------------
__global__ __launch_bounds__(256) void attn_kernel(const int* __restrict__ mask)
{
    __shared__ float Qst[64][64];   // [d][q]
    __shared__ float Ks[64][64];    // [d][k]; reused as Ps[q][k]
    __shared__ float Vs[64][64];    // [k][d]

    const int bh = blockIdx.y;              // 0..63
    const int b  = bh / HH;
    const int h  = bh % HH;
    const int q0 = blockIdx.x * 64;

    const float* Qp = g_Q + (size_t)bh * SS * DD;
    const float* Kp = g_K + (size_t)bh * SS * DD;
    const float* Vp = g_V + (size_t)bh * SS * DD;

    const int tid = threadIdx.x;
    const int ty = tid >> 4;   // 0..15 : q group
    const int tx = tid & 15;   // 0..15 : k / d group

    // Load Q tile transposed
    #pragma unroll
    for (int it = 0; it < 4; it++) {
        int f  = tid + it * 256;       // 0..1023
        int r  = f >> 4;               // 0..63 (q row)
        int d4 = f & 15;
        float4 v = *(const float4*)&Qp[(size_t)(q0 + r) * DD + d4 * 4];
        Qst[d4*4+0][r] = v.x; Qst[d4*4+1][r] = v.y;
        Qst[d4*4+2][r] = v.z; Qst[d4*4+3][r] = v.w;
    }

    float O[4][4];
    float mrow[4], lrow[4];
    #pragma unroll
    for (int i = 0; i < 4; i++) {
        mrow[i] = -1e30f; lrow[i] = 0.f;
        #pragma unroll
        for (int j = 0; j < 4; j++) O[i][j] = 0.f;
    }
    const float qk_scale = 0.125f;   // 1/sqrt(64)

    for (int kc = 0; kc < SS; kc += 64) {
        // Load K (transposed) and V (natural)
        #pragma unroll
        for (int it = 0; it < 4; it++) {
            int f  = tid + it * 256;
            int r  = f >> 4;
            int d4 = f & 15;
            float4 kv = *(const float4*)&Kp[(size_t)(kc + r) * DD + d4 * 4];
            Ks[d4*4+0][r] = kv.x; Ks[d4*4+1][r] = kv.y;
            Ks[d4*4+2][r] = kv.z; Ks[d4*4+3][r] = kv.w;
            float4 vv = *(const float4*)&Vp[(size_t)(kc + r) * DD + d4 * 4];
            *(float4*)&Vs[r][d4*4] = vv;
        }
        __syncthreads();

        // Scores: sc[4q][4k] = Q . K
        float sc[4][4];
        #pragma unroll
        for (int i = 0; i < 4; i++)
            #pragma unroll
            for (int j = 0; j < 4; j++) sc[i][j] = 0.f;

        #pragma unroll 8
        for (int d = 0; d < 64; d++) {
            float4 qv = *(float4*)&Qst[d][ty*4];
            float4 kv = *(float4*)&Ks[d][tx*4];
            float qa[4] = {qv.x, qv.y, qv.z, qv.w};
            float ka[4] = {kv.x, kv.y, kv.z, kv.w};
            #pragma unroll
            for (int i = 0; i < 4; i++)
                #pragma unroll
                for (int j = 0; j < 4; j++)
                    sc[i][j] = fmaf(qa[i], ka[j], sc[i][j]);
        }

        // Mask + clamp
        int mk[4];
        #pragma unroll
        for (int j = 0; j < 4; j++) mk[j] = mask[b * SS + kc + tx*4 + j];
        #pragma unroll
        for (int i = 0; i < 4; i++)
            #pragma unroll
            for (int j = 0; j < 4; j++) {
                float v = sc[i][j] * qk_scale;
                v = fminf(fmaxf(v, -50.f), 50.f);
                sc[i][j] = mk[j] ? v : -50.f;
            }

        // Row max across the 16 tx lanes (same warp half shares ty)
        float rmax[4];
        #pragma unroll
        for (int i = 0; i < 4; i++) {
            float v = fmaxf(fmaxf(sc[i][0], sc[i][1]), fmaxf(sc[i][2], sc[i][3]));
            #pragma unroll
            for (int off = 1; off < 16; off <<= 1)
                v = fmaxf(v, __shfl_xor_sync(0xffffffffu, v, off));
            rmax[i] = v;
        }

        float alpha[4];
        #pragma unroll
        for (int i = 0; i < 4; i++) {
            float mnew = fmaxf(mrow[i], rmax[i]);
            alpha[i] = __expf(mrow[i] - mnew);
            mrow[i] = mnew;
        }

        // p = exp(s - m), partial row sums
        float psum[4];
        #pragma unroll
        for (int i = 0; i < 4; i++) {
            float s = 0.f;
            #pragma unroll
            for (int j = 0; j < 4; j++) {
                float p = __expf(sc[i][j] - mrow[i]);
                sc[i][j] = p;
                s += p;
            }
            #pragma unroll
            for (int off = 1; off < 16; off <<= 1)
                s += __shfl_xor_sync(0xffffffffu, s, off);
            psum[i] = s;
        }
        #pragma unroll
        for (int i = 0; i < 4; i++) lrow[i] = lrow[i] * alpha[i] + psum[i];

        __syncthreads();   // all K reads done before overwriting Ks with P

        // Write P into Ks buffer as Ps[q][k]
        #pragma unroll
        for (int i = 0; i < 4; i++)
            *(float4*)&Ks[ty*4+i][tx*4] = make_float4(sc[i][0], sc[i][1], sc[i][2], sc[i][3]);
        __syncthreads();

        // O = O*alpha + P @ V
        #pragma unroll
        for (int i = 0; i < 4; i++)
            #pragma unroll
            for (int j = 0; j < 4; j++) O[i][j] *= alpha[i];

        #pragma unroll 8
        for (int k = 0; k < 64; k++) {
            float p0 = Ks[ty*4+0][k];
            float p1 = Ks[ty*4+1][k];
            float p2 = Ks[ty*4+2][k];
            float p3 = Ks[ty*4+3][k];
            float4 vv = *(float4*)&Vs[k][tx*4];
            float va[4] = {vv.x, vv.y, vv.z, vv.w};
            #pragma unroll
            for (int j = 0; j < 4; j++) {
                O[0][j] = fmaf(p0, va[j], O[0][j]);
                O[1][j] = fmaf(p1, va[j], O[1][j]);
                O[2][j] = fmaf(p2, va[j], O[2][j]);
                O[3][j] = fmaf(p3, va[j], O[3][j]);
            }
        }
        __syncthreads();   // before next chunk overwrites Ks/Vs
    }

    // Epilogue: normalize, write [B,S,H*D]
    #pragma unroll
    for (int i = 0; i < 4; i++) {
        int q = q0 + ty*4 + i;
        float inv = 1.f / lrow[i];
        float4 o = make_float4(O[i][0]*inv, O[i][1]*inv, O[i][2]*inv, O[i][3]*inv);
        *(float4*)&g_attn[((size_t)(b * SS + q)) * HID + h * 64 + tx * 4] = o;
    }
}

// ---------------------------------------------------------------------------
// Output projection: out = attn @ Wo.T + bo  (plain [M,N] layout)
// ---------------------------------------------------------------------------
__global__ __launch_bounds__(256) void oproj_kernel(
    const float* __restrict__ Wo, const float* __restrict__ bo,
    float* __restrict__ out)
{
    __shared__ float Xs[16][128];
    __shared__ float Ws[16][128];

    const int m0 = blockIdx.x * 128;
    const int n0 = blockIdx.y * 128;
    const int tid = threadIdx.x;
    const int tm = tid >> 4;
    const int tn = tid & 15;

    float acc[8][8];
    #pragma unroll
    for (int i = 0; i < 8; i++)
        #pragma unroll
        for (int j = 0; j < 8; j++) acc[i][j] = 0.f;

    for (int k0 = 0; k0 < HID; k0 += 16) {
        #pragma unroll
        for (int it = 0; it < 2; it++) {
            int f   = tid + it * 256;
            int row = f >> 2;
            int c4  = f & 3;
            float4 xv = *(const float4*)&g_attn[(size_t)(m0 + row) * HID + k0 + c4 * 4];
            Xs[c4*4+0][row] = xv.x; Xs[c4*4+1][row] = xv.y;
            Xs[c4*4+2][row] = xv.z; Xs[c4*4+3][row] = xv.w;
            float4 wv = *(const float4*)&Wo[(size_t)(n0 + row) * HID + k0 + c4 * 4];
            Ws[c4*4+0][row] = wv.x; Ws[c4*4+1][row] = wv.y;
            Ws[c4*4+2][row] = wv.z; Ws[c4*4+3][row] = wv.w;
        }
        __syncthreads();

        #pragma unroll
        for (int kk = 0; kk < 16; kk++) {
            float a[8], w[8];
            *(float4*)&a[0] = *(float4*)&Xs[kk][tm*8];
            *(float4*)&a[4] = *(float4*)&Xs[kk][tm*8+4];
            *(float4*)&w[0] = *(float4*)&Ws[kk][tn*8];
            *(float4*)&w[4] = *(float4*)&Ws[kk][tn*8+4];
            #pragma unroll
            for (int i = 0; i < 8; i++)
                #pragma unroll
                for (int j = 0; j < 8; j++)
                    acc[i][j] = fmaf(a[i], w[j], acc[i][j]);
        }
        __syncthreads();
    }

    #pragma unroll
    for (int i = 0; i < 8; i++) {
        int m = m0 + tm*8 + i;
        #pragma unroll
        for (int j = 0; j < 4; j++) {
            // vectorized 128-bit stores: two float4 per row of 8
        }
        float4 o0, o1;
        int n = n0 + tn*8;
        o0.x = acc[i][0] + bo[n+0]; o0.y = acc[i][1] + bo[n+1];
        o0.z = acc[i][2] + bo[n+2]; o0.w = acc[i][3] + bo[n+3];
        o1.x = acc[i][4] + bo[n+4]; o1.y = acc[i][5] + bo[n+5];
        o1.z = acc[i][6] + bo[n+6]; o1.w = acc[i][7] + bo[n+7];
        *(float4*)&out[(size_t)m * HID + n]     = o0;
        *(float4*)&out[(size_t)m * HID + n + 4] = o1;
    }
}

// ---------------------------------------------------------------------------
extern "C" void kernel_launch(void* const* d_in, const int* in_sizes, int n_in,
                              void* d_out, int out_size)
{
    const float* x    = (const float*)d_in[0];
    const int*   mask = (const int*)  d_in[1];
    const float* Wq   = (const float*)d_in[2];
    const float* bq   = (const float*)d_in[3];
    const float* Wk   = (const float*)d_in[4];
    const float* bk   = (const float*)d_in[5];
    const float* Wv   = (const float*)d_in[6];
    const float* bv   = (const float*)d_in[7];
    const float* Wo   = (const float*)d_in[8];
    const float* bo   = (const float*)d_in[9];
    float* out = (float*)d_out;

    dim3 gq(MTOT/128, HID/128, 3);
    qkv_kernel<<<gq, 256>>>(x, Wq, bq, Wk, bk, Wv, bv);

    dim3 ga(SS/64, BB*HH);
    attn_kernel<<<ga, 256>>>(mask);

    dim3 go(MTOT/128, HID/128);
    oproj_kernel<<<go, 256>>>(Wo, bo, out);
}

// round 3
// speedup vs baseline: 1.6096x; 1.6096x over previous
#include <cuda_runtime.h>
#include <cuda_bf16.h>
#include <cstdint>

#define HID 1024
#define BB  4
#define SS  2048
#define HH  16
#define DD  64
#define MTOT (BB*SS)   // 8192

// ---------------------------------------------------------------------------
// Scratch (__device__ globals; allocation-free rule)
// ---------------------------------------------------------------------------
__device__ float          g_Q[(size_t)BB*HH*SS*DD];   // [B*H, S, D] fp32
__device__ float          g_K[(size_t)BB*HH*SS*DD];
__device__ float          g_V[(size_t)BB*HH*SS*DD];
__device__ float          g_attn[(size_t)MTOT*HID];   // [B*S, HID] fp32
__device__ __nv_bfloat16  g_Xh[(size_t)MTOT*HID];
__device__ __nv_bfloat16  g_Xl[(size_t)MTOT*HID];
__device__ __nv_bfloat16  g_Wh[(size_t)4*HID*HID];    // q,k,v,o packed
__device__ __nv_bfloat16  g_Wl[(size_t)4*HID*HID];
__device__ __nv_bfloat16  g_Ah[(size_t)MTOT*HID];
__device__ __nv_bfloat16  g_Al[(size_t)MTOT*HID];

// ---------------------------------------------------------------------------
// PTX helpers (sm_100-safe: cp.async + ldmatrix + mma.sync only)
// ---------------------------------------------------------------------------
__device__ __forceinline__ uint32_t smem_to_u32(const void* p) {
    uint32_t a;
    asm("{ .reg .u64 t; cvta.to.shared.u64 t, %1; cvt.u32.u64 %0, t; }" : "=r"(a) : "l"(p));
    return a;
}
__device__ __forceinline__ void cp16(uint32_t dst, const void* src) {
    asm volatile("cp.async.ca.shared.global [%0], [%1], 16;" :: "r"(dst), "l"(src));
}
__device__ __forceinline__ void cp_commit() {
    asm volatile("cp.async.commit_group;");
}
template <int N>
__device__ __forceinline__ void cp_wait() {
    asm volatile("cp.async.wait_group %0;" :: "n"(N));
}
__device__ __forceinline__ void ldsm4(uint32_t* r, uint32_t addr) {
    asm volatile("ldmatrix.sync.aligned.m8n8.x4.shared.b16 {%0,%1,%2,%3}, [%4];"
                 : "=r"(r[0]), "=r"(r[1]), "=r"(r[2]), "=r"(r[3]) : "r"(addr));
}
__device__ __forceinline__ void ldsm2(uint32_t* r, uint32_t addr) {
    asm volatile("ldmatrix.sync.aligned.m8n8.x2.shared.b16 {%0,%1}, [%2];"
                 : "=r"(r[0]), "=r"(r[1]) : "r"(addr));
}
__device__ __forceinline__ void mma16816(float* c, const uint32_t* a, const uint32_t* b) {
    asm volatile(
        "mma.sync.aligned.m16n8k16.row.col.f32.bf16.bf16.f32 "
        "{%0,%1,%2,%3}, {%4,%5,%6,%7}, {%8,%9}, {%0,%1,%2,%3};"
        : "+f"(c[0]), "+f"(c[1]), "+f"(c[2]), "+f"(c[3])
        : "r"(a[0]), "r"(a[1]), "r"(a[2]), "r"(a[3]), "r"(b[0]), "r"(b[1]));
}

// ---------------------------------------------------------------------------
// fp32 -> (hi, lo) bf16 split kernels
// ---------------------------------------------------------------------------
__device__ __forceinline__ void split_store(__nv_bfloat16* hi, __nv_bfloat16* lo,
                                            size_t i4, float4 v) {
    __nv_bfloat16 h0 = __float2bfloat16(v.x), h1 = __float2bfloat16(v.y);
    __nv_bfloat16 h2 = __float2bfloat16(v.z), h3 = __float2bfloat16(v.w);
    __nv_bfloat16 l0 = __float2bfloat16(v.x - __bfloat162float(h0));
    __nv_bfloat16 l1 = __float2bfloat16(v.y - __bfloat162float(h1));
    __nv_bfloat16 l2 = __float2bfloat16(v.z - __bfloat162float(h2));
    __nv_bfloat16 l3 = __float2bfloat16(v.w - __bfloat162float(h3));
    ((__nv_bfloat162*)hi)[i4*2]   = __halves2bfloat162(h0, h1);
    ((__nv_bfloat162*)hi)[i4*2+1] = __halves2bfloat162(h2, h3);
    ((__nv_bfloat162*)lo)[i4*2]   = __halves2bfloat162(l0, l1);
    ((__nv_bfloat162*)lo)[i4*2+1] = __halves2bfloat162(l2, l3);
}

__global__ __launch_bounds__(256) void split_x_kernel(const float* __restrict__ src) {
    size_t i = (size_t)blockIdx.x * 256 + threadIdx.x;
    float4 v = ((const float4*)src)[i];
    split_store(g_Xh, g_Xl, i, v);
}
__global__ __launch_bounds__(256) void split_w_kernel(const float* __restrict__ src, int slot) {
    size_t i = (size_t)blockIdx.x * 256 + threadIdx.x;
    float4 v = ((const float4*)src)[i];
    split_store(g_Wh + ((size_t)slot << 20), g_Wl + ((size_t)slot << 20), i, v);
}
__global__ __launch_bounds__(256) void split_a_kernel() {
    size_t i = (size_t)blockIdx.x * 256 + threadIdx.x;
    float4 v = ((const float4*)g_attn)[i];
    split_store(g_Ah, g_Al, i, v);
}

// ---------------------------------------------------------------------------
// mma.sync split-bf16 GEMM:  C[m,n] = sum_k A[m,k]*B[n,k] + bias[n]
// BM=128, BN=128, BK=32; 8 warps as 2(m)x4(n); warp tile 64x32.
// SMEM tiles padded to 40 bf16/row (80B) -> conflict-free ldmatrix.
// ---------------------------------------------------------------------------
#define TPAD   40
#define TILE_B (128 * TPAD * 2)      // 10240 B per tile
#define STAGE_B (4 * TILE_B)         // 40960 B (Ah, Al, Bh, Bl)
#define GEMM_SMEM (2 * STAGE_B)      // 81920 B

__device__ __forceinline__ void gemm_body(
    const __nv_bfloat16* __restrict__ Ah, const __nv_bfloat16* __restrict__ Al,
    const __nv_bfloat16* __restrict__ Bh, const __nv_bfloat16* __restrict__ Bl,
    const float* __restrict__ bias, float* __restrict__ out, int scatter)
{
    extern __shared__ char smem[];
    const uint32_t sb = smem_to_u32(smem);
    const int tid  = threadIdx.x;
    const int wid  = tid >> 5, lane = tid & 31;
    const int wm   = wid >> 2, wn = wid & 3;        // 2 x 4 warp grid
    const int m0 = blockIdx.x * 128, n0 = blockIdx.y * 128;

    const __nv_bfloat16* srcs[4] = {
        Ah + (size_t)m0 * HID, Al + (size_t)m0 * HID,
        Bh + (size_t)n0 * HID, Bl + (size_t)n0 * HID };

    // cp.async stage loader: 4 tiles x 128 rows x 4 chunks of 16B
    auto load_stage = [&](int kc, int s) {
        uint32_t base = sb + s * STAGE_B;
        #pragma unroll
        for (int t = 0; t < 4; t++) {
            #pragma unroll
            for (int it = 0; it < 2; it++) {
                int idx = it * 256 + tid;
                int r = idx >> 2, c = idx & 3;
                cp16(base + t * TILE_B + r * (TPAD * 2) + c * 16,
                     srcs[t] + (size_t)r * HID + kc + c * 8);
            }
        }
    };

    float acc[4][4][4];
    #pragma unroll
    for (int i = 0; i < 4; i++)
        #pragma unroll
        for (int j = 0; j < 4; j++)
            #pragma unroll
            for (int r = 0; r < 4; r++) acc[i][j][r] = 0.f;

    // ldmatrix base offsets (per-thread)
    const int arow = (lane & 15);            // row within 16-row frag
    const int acolh = (lane >> 4);           // 0/1 -> +8 cols
    const int bidx = (lane & 15);
    const int brow = (bidx & 7);
    const int bcolh = (bidx >> 3) & 1;

    load_stage(0, 0);
    cp_commit();

    int cur = 0;
    for (int c = 0; c < 32; c++) {
        if (c + 1 < 32) {
            load_stage((c + 1) * 32, cur ^ 1);
            cp_commit();
            cp_wait<1>();
        } else {
            cp_wait<0>();
        }
        __syncthreads();

        uint32_t base = sb + cur * STAGE_B;
        #pragma unroll
        for (int ks = 0; ks < 2; ks++) {
            uint32_t ah[4][4], al[4][4], bh[4][2], bl[4][2];
            #pragma unroll
            for (int mf = 0; mf < 4; mf++) {
                uint32_t off = (uint32_t)((wm * 64 + mf * 16 + arow) * (TPAD * 2)
                                          + (ks * 16 + acolh * 8) * 2);
                ldsm4(ah[mf], base + 0 * TILE_B + off);
                ldsm4(al[mf], base + 1 * TILE_B + off);
            }
            #pragma unroll
            for (int nf = 0; nf < 4; nf++) {
                uint32_t off = (uint32_t)((wn * 32 + nf * 8 + brow) * (TPAD * 2)
                                          + (ks * 16 + bcolh * 8) * 2);
                ldsm2(bh[nf], base + 2 * TILE_B + off);
                ldsm2(bl[nf], base + 3 * TILE_B + off);
            }
            #pragma unroll
            for (int mf = 0; mf < 4; mf++)
                #pragma unroll
                for (int nf = 0; nf < 4; nf++) {
                    mma16816(acc[mf][nf], ah[mf], bh[nf]);
                    mma16816(acc[mf][nf], ah[mf], bl[nf]);
                    mma16816(acc[mf][nf], al[mf], bh[nf]);
                }
        }
        __syncthreads();
        cur ^= 1;
    }

    // Epilogue: C frag (m16n8): c0,c1 @ (row=lane/4, col=(lane%3)*2...) standard map
    const int crow = lane >> 2;
    const int ccol = (lane & 3) * 2;
    #pragma unroll
    for (int mf = 0; mf < 4; mf++) {
        #pragma unroll
        for (int nf = 0; nf < 4; nf++) {
            int n = n0 + wn * 32 + nf * 8 + ccol;
            float b0 = __ldg(&bias[n]), b1 = __ldg(&bias[n + 1]);
            #pragma unroll
            for (int half = 0; half < 2; half++) {
                int m = m0 + wm * 64 + mf * 16 + crow + half * 8;
                float2 v;
                v.x = acc[mf][nf][half * 2 + 0] + b0;
                v.y = acc[mf][nf][half * 2 + 1] + b1;
                if (scatter) {
                    int b = m >> 11, s = m & 2047;
                    int h = n >> 6, d = n & 63;
                    *(float2*)&out[(((size_t)(b * HH + h)) * SS + s) * DD + d] = v;
                } else {
                    *(float2*)&out[(size_t)m * HID + n] = v;
                }
            }
        }
    }
}

__global__ __launch_bounds__(256) void qkv_mma_kernel(
    const float* __restrict__ bq, const float* __restrict__ bk, const float* __restrict__ bv)
{
    int z = blockIdx.z;
    const float* bias = (z == 0) ? bq : (z == 1) ? bk : bv;
    float* out = (z == 0) ? g_Q : (z == 1) ? g_K : g_V;
    gemm_body(g_Xh, g_Xl, g_Wh + ((size_t)z << 20), g_Wl + ((size_t)z << 20), bias, out, 1);
}
__global__ __launch_bounds__(256) void oproj_mma_kernel(
    const float* __restrict__ bo, float* __restrict__ out)
{
    gemm_body(g_Ah, g_Al, g_Wh + ((size_t)3 << 20), g_Wl + ((size_t)3 << 20), bo, out, 0);
}

// ---------------------------------------------------------------------------
// Flash attention fp32, 128q x 128k tiles, 256 threads, 8qx8k / 8qx4d per thread
// ---------------------------------------------------------------------------
#define KP 132   // padded row width (floats) for transposed Q/K and P
#define ATTN_SMEM ((2*64*KP + 128*64 + 128*KP) * 4)

__global__ __launch_bounds__(256) void attn_kernel2(const int* __restrict__ mask)
{
    extern __shared__ float sm[];
    float* Qst = sm;                          // [64][KP]  (d-major)
    float* Ks  = sm + 64 * KP;                // [64][KP]
    float* Vs  = sm + 2 * 64 * KP;            // [128][64]
    float* Pts = sm + 2 * 64 * KP + 128 * 64; // [128][KP] (k-major, q cols)

    const int bh = blockIdx.y;
    const int b = bh >> 4, h = bh & 15;
    const int q0 = blockIdx.x * 128;
    const float* Qp = g_Q + (size_t)bh * SS * DD;
    const float* Kp = g_K + (size_t)bh * SS * DD;
    const float* Vp = g_V + (size_t)bh * SS * DD;

    const int tid = threadIdx.x;
    const int ty = tid >> 4, tx = tid & 15;

    // Load Q tile transposed
    #pragma unroll
    for (int it = 0; it < 8; it++) {
        int f = it * 256 + tid;
        int r = f >> 4, c4 = f & 15;
        float4 v = *(const float4*)&Qp[(size_t)(q0 + r) * DD + c4 * 4];
        Qst[(c4*4+0)*KP + r] = v.x; Qst[(c4*4+1)*KP + r] = v.y;
        Qst[(c4*4+2)*KP + r] = v.z; Qst[(c4*4+3)*KP + r] = v.w;
    }

    float O[8][4];
    float mrow[8], lrow[8];
    #pragma unroll
    for (int i = 0; i < 8; i++) {
        mrow[i] = -1e30f; lrow[i] = 0.f;
        #pragma unroll
        for (int j = 0; j < 4; j++) O[i][j] = 0.f;
    }

    for (int kc = 0; kc < SS; kc += 128) {
        __syncthreads();
        #pragma unroll
        for (int it = 0; it < 8; it++) {
            int f = it * 256 + tid;
            int r = f >> 4, c4 = f & 15;
            float4 kv = *(const float4*)&Kp[(size_t)(kc + r) * DD + c4 * 4];
            Ks[(c4*4+0)*KP + r] = kv.x; Ks[(c4*4+1)*KP + r] = kv.y;
            Ks[(c4*4+2)*KP + r] = kv.z; Ks[(c4*4+3)*KP + r] = kv.w;
            float4 vv = *(const float4*)&Vp[(size_t)(kc + r) * DD + c4 * 4];
            *(float4*)&Vs[r * 64 + c4 * 4] = vv;
        }
        int4 ma = *(const int4*)&mask[b * SS + kc + tx * 8];
        int4 mb = *(const int4*)&mask[b * SS + kc + tx * 8 + 4];
        __syncthreads();

        float sc[8][8];
        #pragma unroll
        for (int i = 0; i < 8; i++)
            #pragma unroll
            for (int j = 0; j < 8; j++) sc[i][j] = 0.f;

        #pragma unroll 4
        for (int d = 0; d < 64; d++) {
            float4 qa0 = *(float4*)&Qst[d*KP + ty*8];
            float4 qa1 = *(float4*)&Qst[d*KP + ty*8 + 4];
            float4 ka0 = *(float4*)&Ks[d*KP + tx*8];
            float4 ka1 = *(float4*)&Ks[d*KP + tx*8 + 4];
            float qa[8] = {qa0.x,qa0.y,qa0.z,qa0.w,qa1.x,qa1.y,qa1.z,qa1.w};
            float ka[8] = {ka0.x,ka0.y,ka0.z,ka0.w,ka1.x,ka1.y,ka1.z,ka1.w};
            #pragma unroll
            for (int i = 0; i < 8; i++)
                #pragma unroll
                for (int j = 0; j < 8; j++)
                    sc[i][j] = fmaf(qa[i], ka[j], sc[i][j]);
        }

        int mk[8] = {ma.x, ma.y, ma.z, ma.w, mb.x, mb.y, mb.z, mb.w};
        #pragma unroll
        for (int i = 0; i < 8; i++)
            #pragma unroll
            for (int j = 0; j < 8; j++) {
                float v = sc[i][j] * 0.125f;
                v = fminf(fmaxf(v, -50.f), 50.f);
                sc[i][j] = mk[j] ? v : -50.f;
            }

        float alpha[8];
        #pragma unroll
        for (int i = 0; i < 8; i++) {
            float v = fmaxf(fmaxf(fmaxf(sc[i][0], sc[i][1]), fmaxf(sc[i][2], sc[i][3])),
                            fmaxf(fmaxf(sc[i][4], sc[i][5]), fmaxf(sc[i][6], sc[i][7])));
            #pragma unroll
            for (int off = 1; off < 16; off <<= 1)
                v = fmaxf(v, __shfl_xor_sync(0xffffffffu, v, off));
            float mnew = fmaxf(mrow[i], v);
            alpha[i] = __expf(mrow[i] - mnew);
            mrow[i] = mnew;
        }
        #pragma unroll
        for (int i = 0; i < 8; i++) {
            float s = 0.f;
            #pragma unroll
            for (int j = 0; j < 8; j++) {
                float p = __expf(sc[i][j] - mrow[i]);
                sc[i][j] = p;
                s += p;
            }
            #pragma unroll
            for (int off = 1; off < 16; off <<= 1)
                s += __shfl_xor_sync(0xffffffffu, s, off);
            lrow[i] = lrow[i] * alpha[i] + s;
        }

        #pragma unroll
        for (int j = 0; j < 8; j++) {
            int kcol = tx * 8 + j;
            *(float4*)&Pts[kcol*KP + ty*8]     = make_float4(sc[0][j], sc[1][j], sc[2][j], sc[3][j]);
            *(float4*)&Pts[kcol*KP + ty*8 + 4] = make_float4(sc[4][j], sc[5][j], sc[6][j], sc[7][j]);
        }
        __syncthreads();

        #pragma unroll
        for (int i = 0; i < 8; i++)
            #pragma unroll
            for (int j = 0; j < 4; j++) O[i][j] *= alpha[i];

        #pragma unroll 4
        for (int k = 0; k < 128; k++) {
            float4 p0 = *(float4*)&Pts[k*KP + ty*8];
            float4 p1 = *(float4*)&Pts[k*KP + ty*8 + 4];
            float4 vv = *(float4*)&Vs[k*64 + tx*4];
            float pa[8] = {p0.x,p0.y,p0.z,p0.w,p1.x,p1.y,p1.z,p1.w};
            float va[4] = {vv.x,vv.y,vv.z,vv.w};
            #pragma unroll
            for (int i = 0; i < 8; i++)
                #pragma unroll
                for (int j = 0; j < 4; j++)
                    O[i][j] = fmaf(pa[i], va[j], O[i][j]);
        }
    }

    #pragma unroll
    for (int i = 0; i < 8; i++) {
        int q = q0 + ty * 8 + i;
        float inv = 1.f / lrow[i];
        float4 v = make_float4(O[i][0]*inv, O[i][1]*inv, O[i][2]*inv, O[i][3]*inv);
        *(float4*)&g_attn[((size_t)(b * SS + q)) * HID + h * 64 + tx * 4] = v;
    }
}

// ---------------------------------------------------------------------------
extern "C" void kernel_launch(void* const* d_in, const int* in_sizes, int n_in,
                              void* d_out, int out_size)
{
    const float* x    = (const float*)d_in[0];
    const int*   mask = (const int*)  d_in[1];
    const float* Wq   = (const float*)d_in[2];
    const float* bq   = (const float*)d_in[3];
    const float* Wk   = (const float*)d_in[4];
    const float* bk   = (const float*)d_in[5];
    const float* Wv   = (const float*)d_in[6];
    const float* bv   = (const float*)d_in[7];
    const float* Wo   = (const float*)d_in[8];
    const float* bo   = (const float*)d_in[9];
    float* out = (float*)d_out;

    cudaFuncSetAttribute(qkv_mma_kernel,   cudaFuncAttributeMaxDynamicSharedMemorySize, GEMM_SMEM);
    cudaFuncSetAttribute(oproj_mma_kernel, cudaFuncAttributeMaxDynamicSharedMemorySize, GEMM_SMEM);
    cudaFuncSetAttribute(attn_kernel2,     cudaFuncAttributeMaxDynamicSharedMemorySize, ATTN_SMEM);

    split_x_kernel<<<(MTOT*HID/4)/256, 256>>>(x);
    split_w_kernel<<<(HID*HID/4)/256, 256>>>(Wq, 0);
    split_w_kernel<<<(HID*HID/4)/256, 256>>>(Wk, 1);
    split_w_kernel<<<(HID*HID/4)/256, 256>>>(Wv, 2);
    split_w_kernel<<<(HID*HID/4)/256, 256>>>(Wo, 3);

    qkv_mma_kernel<<<dim3(MTOT/128, HID/128, 3), 256, GEMM_SMEM>>>(bq, bk, bv);

    attn_kernel2<<<dim3(SS/128, BB*HH), 256, ATTN_SMEM>>>(mask);

    split_a_kernel<<<(MTOT*HID/4)/256, 256>>>();

    oproj_mma_kernel<<<dim3(MTOT/128, HID/128), 256, GEMM_SMEM>>>(bo, out);
}

// round 4
// speedup vs baseline: 3.2921x; 2.0453x over previous
#include <cuda_runtime.h>
#include <cuda_bf16.h>
#include <cstdint>

#define HID 1024
#define BB  4
#define SS  2048
#define HH  16
#define DD  64
#define MTOT (BB*SS)   // 8192

// ---------------------------------------------------------------------------
// Scratch (__device__ globals; allocation-free rule)
// ---------------------------------------------------------------------------
__device__ __nv_bfloat16  g_Xh[(size_t)MTOT*HID];
__device__ __nv_bfloat16  g_Xl[(size_t)MTOT*HID];
__device__ __nv_bfloat16  g_Wh[(size_t)4*HID*HID];    // q,k,v,o packed
__device__ __nv_bfloat16  g_Wl[(size_t)4*HID*HID];
__device__ __nv_bfloat16  g_Ah[(size_t)MTOT*HID];
__device__ __nv_bfloat16  g_Al[(size_t)MTOT*HID];
// Q/K/V split bf16 in [B*H, S, D]
__device__ __nv_bfloat16  g_Qh[(size_t)BB*HH*SS*DD];
__device__ __nv_bfloat16  g_Ql[(size_t)BB*HH*SS*DD];
__device__ __nv_bfloat16  g_Kh[(size_t)BB*HH*SS*DD];
__device__ __nv_bfloat16  g_Kl[(size_t)BB*HH*SS*DD];
__device__ __nv_bfloat16  g_Vh[(size_t)BB*HH*SS*DD];
__device__ __nv_bfloat16  g_Vl[(size_t)BB*HH*SS*DD];

// ---------------------------------------------------------------------------
// PTX helpers (sm_100-safe: cp.async + ldmatrix + mma.sync only)
// ---------------------------------------------------------------------------
__device__ __forceinline__ uint32_t smem_to_u32(const void* p) {
    uint32_t a;
    asm("{ .reg .u64 t; cvta.to.shared.u64 t, %1; cvt.u32.u64 %0, t; }" : "=r"(a) : "l"(p));
    return a;
}
__device__ __forceinline__ void cp16(uint32_t dst, const void* src) {
    asm volatile("cp.async.ca.shared.global [%0], [%1], 16;" :: "r"(dst), "l"(src));
}
__device__ __forceinline__ void cp_commit() {
    asm volatile("cp.async.commit_group;");
}
template <int N>
__device__ __forceinline__ void cp_wait() {
    asm volatile("cp.async.wait_group %0;" :: "n"(N));
}
__device__ __forceinline__ void ldsm4(uint32_t* r, uint32_t addr) {
    asm volatile("ldmatrix.sync.aligned.m8n8.x4.shared.b16 {%0,%1,%2,%3}, [%4];"
                 : "=r"(r[0]), "=r"(r[1]), "=r"(r[2]), "=r"(r[3]) : "r"(addr));
}
__device__ __forceinline__ void ldsm2(uint32_t* r, uint32_t addr) {
    asm volatile("ldmatrix.sync.aligned.m8n8.x2.shared.b16 {%0,%1}, [%2];"
                 : "=r"(r[0]), "=r"(r[1]) : "r"(addr));
}
__device__ __forceinline__ void ldsm2t(uint32_t* r, uint32_t addr) {
    asm volatile("ldmatrix.sync.aligned.m8n8.x2.trans.shared.b16 {%0,%1}, [%2];"
                 : "=r"(r[0]), "=r"(r[1]) : "r"(addr));
}
__device__ __forceinline__ void mma16816(float* c, const uint32_t* a, const uint32_t* b) {
    asm volatile(
        "mma.sync.aligned.m16n8k16.row.col.f32.bf16.bf16.f32 "
        "{%0,%1,%2,%3}, {%4,%5,%6,%7}, {%8,%9}, {%0,%1,%2,%3};"
        : "+f"(c[0]), "+f"(c[1]), "+f"(c[2]), "+f"(c[3])
        : "r"(a[0]), "r"(a[1]), "r"(a[2]), "r"(a[3]), "r"(b[0]), "r"(b[1]));
}
// pack two floats -> bf16x2 (lo = first), plus residual pack
__device__ __forceinline__ void split2(float a, float b, uint32_t& hi, uint32_t& lo) {
    __nv_bfloat16 ha = __float2bfloat16(a), hb = __float2bfloat16(b);
    float ra = a - __bfloat162float(ha);
    float rb = b - __bfloat162float(hb);
    __nv_bfloat162 H = __halves2bfloat162(ha, hb);
    __nv_bfloat162 L = __halves2bfloat162(__float2bfloat16(ra), __float2bfloat16(rb));
    hi = *(uint32_t*)&H; lo = *(uint32_t*)&L;
}

// ---------------------------------------------------------------------------
// fp32 -> (hi, lo) bf16 split kernels
// ---------------------------------------------------------------------------
__device__ __forceinline__ void split_store(__nv_bfloat16* hi, __nv_bfloat16* lo,
                                            size_t i4, float4 v) {
    uint32_t h0, l0, h1, l1;
    split2(v.x, v.y, h0, l0);
    split2(v.z, v.w, h1, l1);
    ((uint32_t*)hi)[i4*2]   = h0;
    ((uint32_t*)hi)[i4*2+1] = h1;
    ((uint32_t*)lo)[i4*2]   = l0;
    ((uint32_t*)lo)[i4*2+1] = l1;
}

__global__ __launch_bounds__(256) void split_x_kernel(const float* __restrict__ src) {
    size_t i = (size_t)blockIdx.x * 256 + threadIdx.x;
    float4 v = ((const float4*)src)[i];
    split_store(g_Xh, g_Xl, i, v);
}
__global__ __launch_bounds__(256) void split_w_kernel(const float* __restrict__ src, int slot) {
    size_t i = (size_t)blockIdx.x * 256 + threadIdx.x;
    float4 v = ((const float4*)src)[i];
    split_store(g_Wh + ((size_t)slot << 20), g_Wl + ((size_t)slot << 20), i, v);
}

// ---------------------------------------------------------------------------
// mma.sync split-bf16 GEMM:  C[m,n] = sum_k A[m,k]*B[n,k] + bias[n]
// BM=128, BN=128, BK=32; 8 warps as 2(m)x4(n); warp tile 64x32.
// SMEM tiles padded to 40 bf16/row (80B) -> conflict-free ldmatrix.
// SCATTER=1: emit bf16 hi/lo into [B,H,S,D]; SCATTER=0: fp32 row-major.
// ---------------------------------------------------------------------------
#define TPAD   40
#define TILE_B (128 * TPAD * 2)      // 10240 B per tile
#define STAGE_B (4 * TILE_B)         // 40960 B (Ah, Al, Bh, Bl)
#define GEMM_SMEM (2 * STAGE_B)      // 81920 B

template <int SCATTER>
__device__ __forceinline__ void gemm_body(
    const __nv_bfloat16* __restrict__ Ah, const __nv_bfloat16* __restrict__ Al,
    const __nv_bfloat16* __restrict__ Bh, const __nv_bfloat16* __restrict__ Bl,
    const float* __restrict__ bias, float* __restrict__ outF,
    __nv_bfloat16* __restrict__ outH, __nv_bfloat16* __restrict__ outL)
{
    extern __shared__ char smem[];
    const uint32_t sb = smem_to_u32(smem);
    const int tid  = threadIdx.x;
    const int wid  = tid >> 5, lane = tid & 31;
    const int wm   = wid >> 2, wn = wid & 3;        // 2 x 4 warp grid
    const int m0 = blockIdx.x * 128, n0 = blockIdx.y * 128;

    const __nv_bfloat16* srcs[4] = {
        Ah + (size_t)m0 * HID, Al + (size_t)m0 * HID,
        Bh + (size_t)n0 * HID, Bl + (size_t)n0 * HID };

    auto load_stage = [&](int kc, int s) {
        uint32_t base = sb + s * STAGE_B;
        #pragma unroll
        for (int t = 0; t < 4; t++) {
            #pragma unroll
            for (int it = 0; it < 2; it++) {
                int idx = it * 256 + tid;
                int r = idx >> 2, c = idx & 3;
                cp16(base + t * TILE_B + r * (TPAD * 2) + c * 16,
                     srcs[t] + (size_t)r * HID + kc + c * 8);
            }
        }
    };

    float acc[4][4][4];
    #pragma unroll
    for (int i = 0; i < 4; i++)
        #pragma unroll
        for (int j = 0; j < 4; j++)
            #pragma unroll
            for (int r = 0; r < 4; r++) acc[i][j][r] = 0.f;

    const int arow = (lane & 15);
    const int acolh = (lane >> 4);
    const int brow = (lane & 7);
    const int bcolh = (lane >> 3) & 1;

    load_stage(0, 0);
    cp_commit();

    int cur = 0;
    for (int c = 0; c < 32; c++) {
        if (c + 1 < 32) {
            load_stage((c + 1) * 32, cur ^ 1);
            cp_commit();
            cp_wait<1>();
        } else {
            cp_wait<0>();
        }
        __syncthreads();

        uint32_t base = sb + cur * STAGE_B;
        #pragma unroll
        for (int ks = 0; ks < 2; ks++) {
            uint32_t ah[4][4], al[4][4], bh[4][2], bl[4][2];
            #pragma unroll
            for (int mf = 0; mf < 4; mf++) {
                uint32_t off = (uint32_t)((wm * 64 + mf * 16 + arow) * (TPAD * 2)
                                          + (ks * 16 + acolh * 8) * 2);
                ldsm4(ah[mf], base + 0 * TILE_B + off);
                ldsm4(al[mf], base + 1 * TILE_B + off);
            }
            #pragma unroll
            for (int nf = 0; nf < 4; nf++) {
                uint32_t off = (uint32_t)((wn * 32 + nf * 8 + brow) * (TPAD * 2)
                                          + (ks * 16 + bcolh * 8) * 2);
                ldsm2(bh[nf], base + 2 * TILE_B + off);
                ldsm2(bl[nf], base + 3 * TILE_B + off);
            }
            #pragma unroll
            for (int mf = 0; mf < 4; mf++)
                #pragma unroll
                for (int nf = 0; nf < 4; nf++) {
                    mma16816(acc[mf][nf], ah[mf], bh[nf]);
                    mma16816(acc[mf][nf], ah[mf], bl[nf]);
                    mma16816(acc[mf][nf], al[mf], bh[nf]);
                }
        }
        __syncthreads();
        cur ^= 1;
    }

    const int crow = lane >> 2;
    const int ccol = (lane & 3) * 2;
    #pragma unroll
    for (int mf = 0; mf < 4; mf++) {
        #pragma unroll
        for (int nf = 0; nf < 4; nf++) {
            int n = n0 + wn * 32 + nf * 8 + ccol;
            float b0 = __ldg(&bias[n]), b1 = __ldg(&bias[n + 1]);
            #pragma unroll
            for (int half = 0; half < 2; half++) {
                int m = m0 + wm * 64 + mf * 16 + crow + half * 8;
                float v0 = acc[mf][nf][half * 2 + 0] + b0;
                float v1 = acc[mf][nf][half * 2 + 1] + b1;
                if (SCATTER) {
                    int b = m >> 11, s = m & 2047;
                    int h = n >> 6, d = n & 63;
                    size_t o = (((size_t)(b * HH + h)) * SS + s) * DD + d;
                    uint32_t hi, lo;
                    split2(v0, v1, hi, lo);
                    *(uint32_t*)&outH[o] = hi;
                    *(uint32_t*)&outL[o] = lo;
                } else {
                    float2 v; v.x = v0; v.y = v1;
                    *(float2*)&outF[(size_t)m * HID + n] = v;
                }
            }
        }
    }
}

__global__ __launch_bounds__(256) void qkv_mma_kernel(
    const float* __restrict__ bq, const float* __restrict__ bk, const float* __restrict__ bv)
{
    int z = blockIdx.z;
    const float* bias = (z == 0) ? bq : (z == 1) ? bk : bv;
    __nv_bfloat16* oh = (z == 0) ? g_Qh : (z == 1) ? g_Kh : g_Vh;
    __nv_bfloat16* ol = (z == 0) ? g_Ql : (z == 1) ? g_Kl : g_Vl;
    gemm_body<1>(g_Xh, g_Xl, g_Wh + ((size_t)z << 20), g_Wl + ((size_t)z << 20),
                 bias, nullptr, oh, ol);
}
__global__ __launch_bounds__(256) void oproj_mma_kernel(
    const float* __restrict__ bo, float* __restrict__ out)
{
    gemm_body<0>(g_Ah, g_Al, g_Wh + ((size_t)3 << 20), g_Wl + ((size_t)3 << 20),
                 bo, out, nullptr, nullptr);
}

// ---------------------------------------------------------------------------
// Flash attention with mma.sync, split bf16.
// Block: 128 queries of one (b,h); 8 warps x 16q. K chunks of 128.
// SMEM: double-buffered Kh/Kl/Vh/Vl [128][72] bf16 + mask; Q staged once.
// ---------------------------------------------------------------------------
#define APAD   72
#define AROWB  (APAD * 2)            // 144 B/row
#define KV_TILE (128 * AROWB)        // 18432 B
#define STAGEA (4 * KV_TILE)         // 73728 B
#define ATTN_SMEM (2 * STAGEA + 2 * 128 * 4)   // 148480 B

__global__ __launch_bounds__(256, 1) void attn_mma_kernel(const int* __restrict__ mask)
{
    extern __shared__ char sm8[];
    const uint32_t sb = smem_to_u32(sm8);
    const int tid = threadIdx.x;
    const int wid = tid >> 5, lane = tid & 31;
    const int bh = blockIdx.y;
    const int b = bh >> 4, h = bh & 15;
    const int q0 = blockIdx.x * 128;

    const __nv_bfloat16* Qhp = g_Qh + (size_t)bh * SS * DD;
    const __nv_bfloat16* Qlp = g_Ql + (size_t)bh * SS * DD;
    const __nv_bfloat16* Khp = g_Kh + (size_t)bh * SS * DD;
    const __nv_bfloat16* Klp = g_Kl + (size_t)bh * SS * DD;
    const __nv_bfloat16* Vhp = g_Vh + (size_t)bh * SS * DD;
    const __nv_bfloat16* Vlp = g_Vl + (size_t)bh * SS * DD;

    // ---- stage Q into stage-0 K region, extract fragments ----
    #pragma unroll
    for (int it = 0; it < 4; it++) {
        int idx = it * 256 + tid;
        int r = idx >> 3, c = idx & 7;
        cp16(sb + r * AROWB + c * 16,            Qhp + (size_t)(q0 + r) * DD + c * 8);
        cp16(sb + KV_TILE + r * AROWB + c * 16,  Qlp + (size_t)(q0 + r) * DD + c * 8);
    }
    cp_commit();
    cp_wait<0>();
    __syncthreads();

    uint32_t qh[4][4], ql[4][4];
    const int arow = lane & 15, acolh = lane >> 4;
    #pragma unroll
    for (int kf = 0; kf < 4; kf++) {
        uint32_t off = (uint32_t)((wid * 16 + arow) * AROWB + (kf * 16 + acolh * 8) * 2);
        ldsm4(qh[kf], sb + off);
        ldsm4(ql[kf], sb + KV_TILE + off);
    }
    __syncthreads();

    // ---- K/V chunk loader ----
    auto load_kv = [&](int kc, int s) {
        uint32_t base = sb + s * STAGEA;
        #pragma unroll
        for (int it = 0; it < 4; it++) {
            int idx = it * 256 + tid;
            int r = idx >> 3, c = idx & 7;
            size_t g = (size_t)(kc + r) * DD + c * 8;
            uint32_t so = r * AROWB + c * 16;
            cp16(base + 0 * KV_TILE + so, Khp + g);
            cp16(base + 1 * KV_TILE + so, Klp + g);
            cp16(base + 2 * KV_TILE + so, Vhp + g);
            cp16(base + 3 * KV_TILE + so, Vlp + g);
        }
        if (tid < 32)
            cp16(sb + 2 * STAGEA + s * 512 + tid * 16, mask + (size_t)b * SS + kc + tid * 4);
    };

    load_kv(0, 0);
    cp_commit();

    float O[8][4];
    #pragma unroll
    for (int i = 0; i < 8; i++)
        #pragma unroll
        for (int j = 0; j < 4; j++) O[i][j] = 0.f;
    float mrow0 = -1e30f, mrow1 = -1e30f, lrow0 = 0.f, lrow1 = 0.f;

    for (int c = 0; c < SS / 128; c++) {
        int cur = c & 1;
        cp_wait<0>();
        __syncthreads();
        if (c + 1 < SS / 128) {
            load_kv((c + 1) * 128, cur ^ 1);
            cp_commit();
        }

        // ---- S = Q K^T (split bf16, 3 products) ----
        float sacc[16][4];
        #pragma unroll
        for (int nf = 0; nf < 16; nf++)
            #pragma unroll
            for (int r = 0; r < 4; r++) sacc[nf][r] = 0.f;

        uint32_t kbh = sb + cur * STAGEA;
        uint32_t kbl = kbh + KV_TILE;
        #pragma unroll
        for (int nf = 0; nf < 16; nf++) {
            #pragma unroll
            for (int kf = 0; kf < 4; kf++) {
                uint32_t kh2[2], kl2[2];
                uint32_t off = (uint32_t)((nf * 8 + (lane & 7)) * AROWB
                                          + (kf * 16 + ((lane >> 3) & 1) * 8) * 2);
                ldsm2(kh2, kbh + off);
                ldsm2(kl2, kbl + off);
                mma16816(sacc[nf], qh[kf], kh2);
                mma16816(sacc[nf], qh[kf], kl2);
                mma16816(sacc[nf], ql[kf], kh2);
            }
        }

        // ---- mask + clamp + online softmax (rows r0=lane/4, r1=r0+8) ----
        const int* msk = (const int*)(sm8 + 2 * STAGEA + cur * 512);
        float mx0 = -1e30f, mx1 = -1e30f;
        #pragma unroll
        for (int nf = 0; nf < 16; nf++) {
            int n = nf * 8 + (lane & 3) * 2;
            int mk0 = msk[n], mk1 = msk[n + 1];
            float v;
            v = sacc[nf][0] * 0.125f; v = fminf(fmaxf(v, -50.f), 50.f);
            v = mk0 ? v : -50.f; sacc[nf][0] = v; mx0 = fmaxf(mx0, v);
            v = sacc[nf][1] * 0.125f; v = fminf(fmaxf(v, -50.f), 50.f);
            v = mk1 ? v : -50.f; sacc[nf][1] = v; mx0 = fmaxf(mx0, v);
            v = sacc[nf][2] * 0.125f; v = fminf(fmaxf(v, -50.f), 50.f);
            v = mk0 ? v : -50.f; sacc[nf][2] = v; mx1 = fmaxf(mx1, v);
            v = sacc[nf][3] * 0.125f; v = fminf(fmaxf(v, -50.f), 50.f);
            v = mk1 ? v : -50.f; sacc[nf][3] = v; mx1 = fmaxf(mx1, v);
        }
        mx0 = fmaxf(mx0, __shfl_xor_sync(0xffffffffu, mx0, 1));
        mx0 = fmaxf(mx0, __shfl_xor_sync(0xffffffffu, mx0, 2));
        mx1 = fmaxf(mx1, __shfl_xor_sync(0xffffffffu, mx1, 1));
        mx1 = fmaxf(mx1, __shfl_xor_sync(0xffffffffu, mx1, 2));

        float mn0 = fmaxf(mrow0, mx0), mn1 = fmaxf(mrow1, mx1);
        float a0 = __expf(mrow0 - mn0), a1 = __expf(mrow1 - mn1);
        mrow0 = mn0; mrow1 = mn1;

        float s0 = 0.f, s1 = 0.f;
        #pragma unroll
        for (int nf = 0; nf < 16; nf++) {
            float p;
            p = __expf(sacc[nf][0] - mn0); sacc[nf][0] = p; s0 += p;
            p = __expf(sacc[nf][1] - mn0); sacc[nf][1] = p; s0 += p;
            p = __expf(sacc[nf][2] - mn1); sacc[nf][2] = p; s1 += p;
            p = __expf(sacc[nf][3] - mn1); sacc[nf][3] = p; s1 += p;
        }
        s0 += __shfl_xor_sync(0xffffffffu, s0, 1);
        s0 += __shfl_xor_sync(0xffffffffu, s0, 2);
        s1 += __shfl_xor_sync(0xffffffffu, s1, 1);
        s1 += __shfl_xor_sync(0xffffffffu, s1, 2);
        lrow0 = lrow0 * a0 + s0;
        lrow1 = lrow1 * a1 + s1;

        #pragma unroll
        for (int nf = 0; nf < 8; nf++) {
            O[nf][0] *= a0; O[nf][1] *= a0;
            O[nf][2] *= a1; O[nf][3] *= a1;
        }

        // ---- O += P V (P split from registers, V via ldmatrix.trans) ----
        uint32_t vbh = kbh + 2 * KV_TILE;
        #pragma unroll
        for (int kk = 0; kk < 8; kk++) {
            uint32_t ah4[4], al4[4];
            float* f0 = sacc[2 * kk];
            float* f1 = sacc[2 * kk + 1];
            split2(f0[0], f0[1], ah4[0], al4[0]);
            split2(f0[2], f0[3], ah4[1], al4[1]);
            split2(f1[0], f1[1], ah4[2], al4[2]);
            split2(f1[2], f1[3], ah4[3], al4[3]);
            uint32_t vrow = (uint32_t)((kk * 16 + (lane & 15)) * AROWB);
            #pragma unroll
            for (int nf = 0; nf < 8; nf++) {
                uint32_t vh2[2], vl2[2];
                uint32_t va = vbh + vrow + nf * 16;
                ldsm2t(vh2, va);
                ldsm2t(vl2, va + KV_TILE);
                mma16816(O[nf], ah4, vh2);
                mma16816(O[nf], al4, vh2);
                mma16816(O[nf], ah4, vl2);
            }
        }
        __syncthreads();  // all reads of cur done before it is refilled next+1
    }

    // ---- epilogue: normalize, split to bf16 hi/lo, write [B,S,HID] ----
    float inv0 = 1.f / lrow0, inv1 = 1.f / lrow1;
    int qr0 = q0 + wid * 16 + (lane >> 2);
    size_t rowA0 = ((size_t)(b * SS + qr0)) * HID + h * 64;
    size_t rowA1 = ((size_t)(b * SS + qr0 + 8)) * HID + h * 64;
    #pragma unroll
    for (int nf = 0; nf < 8; nf++) {
        int n = nf * 8 + (lane & 3) * 2;
        uint32_t hi, lo;
        split2(O[nf][0] * inv0, O[nf][1] * inv0, hi, lo);
        *(uint32_t*)&g_Ah[rowA0 + n] = hi;
        *(uint32_t*)&g_Al[rowA0 + n] = lo;
        split2(O[nf][2] * inv1, O[nf][3] * inv1, hi, lo);
        *(uint32_t*)&g_Ah[rowA1 + n] = hi;
        *(uint32_t*)&g_Al[rowA1 + n] = lo;
    }
}

// ---------------------------------------------------------------------------
extern "C" void kernel_launch(void* const* d_in, const int* in_sizes, int n_in,
                              void* d_out, int out_size)
{
    const float* x    = (const float*)d_in[0];
    const int*   mask = (const int*)  d_in[1];
    const float* Wq   = (const float*)d_in[2];
    const float* bq   = (const float*)d_in[3];
    const float* Wk   = (const float*)d_in[4];
    const float* bk   = (const float*)d_in[5];
    const float* Wv   = (const float*)d_in[6];
    const float* bv   = (const float*)d_in[7];
    const float* Wo   = (const float*)d_in[8];
    const float* bo   = (const float*)d_in[9];
    float* out = (float*)d_out;

    cudaFuncSetAttribute(qkv_mma_kernel,   cudaFuncAttributeMaxDynamicSharedMemorySize, GEMM_SMEM);
    cudaFuncSetAttribute(oproj_mma_kernel, cudaFuncAttributeMaxDynamicSharedMemorySize, GEMM_SMEM);
    cudaFuncSetAttribute(attn_mma_kernel,  cudaFuncAttributeMaxDynamicSharedMemorySize, ATTN_SMEM);

    split_x_kernel<<<(MTOT*HID/4)/256, 256>>>(x);
    split_w_kernel<<<(HID*HID/4)/256, 256>>>(Wq, 0);
    split_w_kernel<<<(HID*HID/4)/256, 256>>>(Wk, 1);
    split_w_kernel<<<(HID*HID/4)/256, 256>>>(Wv, 2);
    split_w_kernel<<<(HID*HID/4)/256, 256>>>(Wo, 3);

    qkv_mma_kernel<<<dim3(MTOT/128, HID/128, 3), 256, GEMM_SMEM>>>(bq, bk, bv);

    attn_mma_kernel<<<dim3(SS/128, BB*HH), 256, ATTN_SMEM>>>(mask);

    oproj_mma_kernel<<<dim3(MTOT/128, HID/128), 256, GEMM_SMEM>>>(bo, out);
}